// round 11
// baseline (speedup 1.0000x reference)
#include <cuda_runtime.h>

#define B_  4
#define N_  2048
#define V_  12
#define C_  50
#define P_  16384   /* H*W = 128*128 */
#define RSL 6       /* log2 row stride: 64 floats = 256 B aligned rows */
#define GN_ 8       /* n-items per lift block (= warps per block) */

// Winner keys, encoded key+1 so 0 == "no winner". Statically zero-initialized;
// lift resets each entry to 0 after reading -> clean state every replay.
__device__ int g_winner[B_ * V_ * N_];

// Per-(bv,pixel) RAW logit rows (50 floats used, 64 stride), written only for
// mask-passing pixels (~7%). Cols 50..63 never written -> always zero.
__device__ float g_feat[((size_t)B_ * V_ * P_) << RSL];   // ~201 MB
// Never written -> always zero. Target for views without a winner.
__device__ float g_zero[1 << RSL];

// K1 — one thread per pixel of ONE batch, single pass, x[50] in registers.
// NO early returns (R8: worth 18us). Body identical to the measured R8/R10
// form; only the batch offset is parameterized.
__global__ __launch_bounds__(256) void argmax_scatter_kernel(
    const float* __restrict__ pred,        // (B,V,C,P)
    const int*   __restrict__ p2p,         // (B,V,P)
    const int*   __restrict__ parts_nb,    // (B,)
    int bb)
{
    int t  = blockIdx.x * blockDim.x + threadIdx.x;   // [0, V*P)
    int bv = bb * V_ + (t >> 14);          // global view index
    int p  = t & (P_ - 1);

    int point = __ldcs(&p2p[(size_t)bv * P_ + p]);    // alongside pred loads
    int pn    = parts_nb[bb];

    const float* base = pred + (size_t)bv * C_ * P_ + p;
    float x[C_];
    float mx = -3.402823466e+38f;
    int   am = 0;
#pragma unroll
    for (int c = 0; c < C_; c++) {
        x[c] = __ldcs(&base[(size_t)c * P_]);
        if (x[c] > mx) { mx = x[c]; am = c; }   // '>' keeps first occurrence (jnp.argmax)
    }

    if (point >= 0 && am >= 1 && am <= pn) {
        float* row = g_feat + (((size_t)bv * P_ + p) << RSL);   // 256B-aligned
        float4* r4 = (float4*)row;
#pragma unroll
        for (int c4 = 0; c4 < C_ / 4; c4++)         // 48 floats as STG.128
            r4[c4] = make_float4(x[4*c4], x[4*c4+1], x[4*c4+2], x[4*c4+3]);
        ((float2*)row)[24] = make_float2(x[48], x[49]);

        int key = am * P_ + p + 1;             // +1: 0 means "no winner"
        atomicMax(&g_winner[bv * N_ + (point & (N_ - 1))], key);
    }
}

// K2 — fused lift for ONE batch (R10-measured form, batch parameterized):
// reciprocal denom in s_dn, FMUL in phase 3.
__global__ __launch_bounds__(256) void lift_kernel(
    const float* __restrict__ vw,          // (B,V)
    float*       __restrict__ out,         // (B,C,N)
    int b)
{
    const unsigned FULL = 0xFFFFFFFFu;
    int n0   = blockIdx.x * GN_;
    int wid  = threadIdx.x >> 5;
    int lane = threadIdx.x & 31;
    int n    = n0 + wid;

    __shared__ float s_row[GN_][V_][64];   // 24.5 KB staged rows
    __shared__ float s_acc[C_][GN_ + 1];   // +1 pad: conflict-free transpose
    __shared__ float s_dn[GN_];            // reciprocal of denom

    // phase 0
    int key = 0;
    float w = 0.f;
    if (lane < V_) {
        int* wp = &g_winner[(b * V_ + lane) * N_ + n];
        key = *wp;
        *wp = 0;                           // reset for next graph replay
        w = vw[b * V_ + lane];
    }
    unsigned ball = __ballot_sync(FULL, key > 0);
    float denom = fmaxf((float)__popc(ball), 1.f);

    // phase 1: stage all 12 rows (24 independent loads), same-lane smem slots
#pragma unroll
    for (int v = 0; v < V_; v++) {
        int kv = __shfl_sync(FULL, key, v);
        const float* row = (kv > 0)
            ? g_feat + (((size_t)(b * V_ + v) * P_ + ((kv - 1) & (P_ - 1))) << RSL)
            : g_zero;
        s_row[wid][v][lane]      = __ldg(&row[lane]);
        s_row[wid][v][lane + 32] = __ldg(&row[lane + 32]);
    }

    // phase 2: softmax per view from smem + weighted accumulate
    float acc0 = 0.f, acc1 = 0.f;
#pragma unroll
    for (int v = 0; v < V_; v++) {
        int   kv = __shfl_sync(FULL, key, v);
        float wv = __shfl_sync(FULL, w,   v);
        float e0 = __expf(s_row[wid][v][lane]);
        float e1 = (lane + 32 < C_) ? __expf(s_row[wid][v][lane + 32]) : 0.f;
        float se = e0 + e1;
#pragma unroll
        for (int s = 16; s >= 1; s >>= 1)
            se += __shfl_xor_sync(FULL, se, s);
        float inv = (kv > 0) ? __fdividef(wv, se) : 0.f;
        acc0 += inv * e0;
        acc1 += inv * e1;
    }

    s_acc[lane][wid] = acc0;
    if (lane + 32 < C_) s_acc[lane + 32][wid] = acc1;
    if (lane == 0) s_dn[wid] = __fdividef(1.0f, denom);   // reciprocal, once/warp
    __syncthreads();

    // phase 3: 400 outputs per block, coalesced along n, FMUL not FDIV
#pragma unroll
    for (int i = threadIdx.x; i < C_ * GN_; i += 256) {
        int c = i >> 3, j = i & (GN_ - 1);
        out[((size_t)b * C_ + c) * N_ + n0 + j] = s_acc[c][j] * s_dn[j];
    }
}

// Host-side stream/event objects, created ONCE at static-init time (before the
// harness's memory checkpoints; host objects only — no device allocations in
// kernel_launch). Reused identically on every call -> deterministic work.
static cudaStream_t g_str[B_];
static cudaEvent_t  g_root, g_done[B_];
static const bool g_once = []() {
    for (int i = 0; i < B_; i++)
        cudaStreamCreateWithFlags(&g_str[i], cudaStreamNonBlocking);
    cudaEventCreateWithFlags(&g_root, cudaEventDisableTiming);
    for (int i = 0; i < B_; i++)
        cudaEventCreateWithFlags(&g_done[i], cudaEventDisableTiming);
    return true;
}();

extern "C" void kernel_launch(void* const* d_in, const int* in_sizes, int n_in,
                              void* d_out, int out_size) {
    // inputs: 0 points (unused), 1 predictions_2d, 2 rendered_pix_to_point,
    //         3 views_weights, 4 parts_nb
    const float* pred     = (const float*)d_in[1];
    const int*   p2p      = (const int*)  d_in[2];
    const float* vw       = (const float*)d_in[3];
    const int*   parts_nb = (const int*)  d_in[4];
    float*       out      = (float*)d_out;

    (void)g_once;

    // Fork: per-batch scatter->lift chains on 4 streams; lifts for batch b
    // overlap scatters for batches > b. Joined back to the launch stream.
    cudaEventRecord(g_root, 0);
    for (int b = 0; b < B_; b++) {
        cudaStreamWaitEvent(g_str[b], g_root, 0);
        argmax_scatter_kernel<<<(V_ * P_) / 256, 256, 0, g_str[b]>>>(
            pred, p2p, parts_nb, b);
        lift_kernel<<<N_ / GN_, 256, 0, g_str[b]>>>(vw, out, b);
        cudaEventRecord(g_done[b], g_str[b]);
    }
    for (int b = 0; b < B_; b++)
        cudaStreamWaitEvent(0, g_done[b], 0);
}

// round 12
// speedup vs baseline: 1.0637x; 1.0637x over previous
#include <cuda_runtime.h>

#define B_  4
#define N_  2048
#define V_  12
#define C_  50
#define P_  16384   /* H*W = 128*128 */
#define RSL 6       /* log2 row stride: 64 floats = 256 B aligned rows */

// Winner keys, encoded key+1 so 0 == "no winner". Statically zero-initialized;
// lift resets each entry to 0 after reading -> clean state every replay.
__device__ int g_winner[B_ * V_ * N_];

// Per-(bv,pixel) RAW logit rows (50 floats used, 64 stride), written only for
// mask-passing pixels (~7%). Cols 50..63 never written -> always zero.
__device__ float g_feat[((size_t)B_ * V_ * P_) << RSL];   // ~201 MB
// Never written -> always zero. Target for views without a winner.
__device__ float g_zero[1 << RSL];

// K1 — one thread per pixel of ONE batch, single pass, x[50] in registers.
// NO early returns (R8: worth 18us). Measured form, batch-parameterized.
__global__ __launch_bounds__(256) void argmax_scatter_kernel(
    const float* __restrict__ pred,        // (B,V,C,P)
    const int*   __restrict__ p2p,         // (B,V,P)
    const int*   __restrict__ parts_nb,    // (B,)
    int bb)
{
    int t  = blockIdx.x * blockDim.x + threadIdx.x;   // [0, V*P)
    int bv = bb * V_ + (t >> 14);          // global view index
    int p  = t & (P_ - 1);

    int point = __ldcs(&p2p[(size_t)bv * P_ + p]);    // alongside pred loads
    int pn    = parts_nb[bb];

    const float* base = pred + (size_t)bv * C_ * P_ + p;
    float x[C_];
    float mx = -3.402823466e+38f;
    int   am = 0;
#pragma unroll
    for (int c = 0; c < C_; c++) {
        x[c] = __ldcs(&base[(size_t)c * P_]);
        if (x[c] > mx) { mx = x[c]; am = c; }   // '>' keeps first occurrence (jnp.argmax)
    }

    if (point >= 0 && am >= 1 && am <= pn) {
        float* row = g_feat + (((size_t)bv * P_ + p) << RSL);   // 256B-aligned
        float4* r4 = (float4*)row;
#pragma unroll
        for (int c4 = 0; c4 < C_ / 4; c4++)         // 48 floats as STG.128
            r4[c4] = make_float4(x[4*c4], x[4*c4+1], x[4*c4+2], x[4*c4+3]);
        ((float2*)row)[24] = make_float2(x[48], x[49]);

        int key = am * P_ + p + 1;             // +1: 0 means "no winner"
        atomicMax(&g_winner[bv * N_ + (point & (N_ - 1))], key);
    }
}

// K2 — lift for ONE batch, TWO WARPS per n (6 views each) to double warp
// parallelism (per-batch lift was latency-bound at 14 warps/SM). 8 warps per
// block -> 4 n-slots/block, 512 blocks/batch, ~28 warps/SM.
__global__ __launch_bounds__(256) void lift_kernel(
    const float* __restrict__ vw,          // (B,V)
    float*       __restrict__ out,         // (B,C,N)
    int b)
{
    const unsigned FULL = 0xFFFFFFFFu;
    int wid  = threadIdx.x >> 5;
    int lane = threadIdx.x & 31;
    int slot = wid >> 1;                   // 0..3: n within block
    int half = wid & 1;                    // 0/1: views [0,6) or [6,12)
    int n    = blockIdx.x * 4 + slot;

    __shared__ float s_row[4][V_][64];     // 12 KB staged rows
    __shared__ float s_par[4][2][64];      // per-half partial accumulators
    __shared__ float s_cnt[4][2];
    __shared__ float s_acc[C_][5];         // +pad: transpose for output

    // phase 0: lanes 0..5 read+reset winner keys for this half's views
    int key = 0;
    float w = 0.f;
    if (lane < 6) {
        int v = half * 6 + lane;
        int* wp = &g_winner[(b * V_ + v) * N_ + n];
        key = *wp;
        *wp = 0;                           // reset for next graph replay
        w = vw[b * V_ + v];
    }
    unsigned ball = __ballot_sync(FULL, key > 0);
    float cnt = (float)__popc(ball);

    // phase 1: stage this half's 6 rows (12 independent loads)
#pragma unroll
    for (int vl = 0; vl < 6; vl++) {
        int v  = half * 6 + vl;
        int kv = __shfl_sync(FULL, key, vl);
        const float* row = (kv > 0)
            ? g_feat + (((size_t)(b * V_ + v) * P_ + ((kv - 1) & (P_ - 1))) << RSL)
            : g_zero;
        s_row[slot][v][lane]      = __ldg(&row[lane]);
        s_row[slot][v][lane + 32] = __ldg(&row[lane + 32]);
    }

    // phase 2: softmax per view from smem + weighted accumulate (6 views)
    float acc0 = 0.f, acc1 = 0.f;
#pragma unroll
    for (int vl = 0; vl < 6; vl++) {
        int   v  = half * 6 + vl;
        int   kv = __shfl_sync(FULL, key, vl);
        float wv = __shfl_sync(FULL, w,   vl);
        float e0 = __expf(s_row[slot][v][lane]);
        float e1 = (lane + 32 < C_) ? __expf(s_row[slot][v][lane + 32]) : 0.f;
        float se = e0 + e1;
#pragma unroll
        for (int s = 16; s >= 1; s >>= 1)
            se += __shfl_xor_sync(FULL, se, s);
        float inv = (kv > 0) ? __fdividef(wv, se) : 0.f;
        acc0 += inv * e0;
        acc1 += inv * e1;
    }
    s_par[slot][half][lane]      = acc0;
    s_par[slot][half][lane + 32] = acc1;
    if (lane == 0) s_cnt[slot][half] = cnt;
    __syncthreads();

    // combine halves (even warps), fold reciprocal denom, transpose
    if (half == 0) {
        float rdn = __fdividef(1.0f,
            fmaxf(s_cnt[slot][0] + s_cnt[slot][1], 1.f));
        float a0 = (s_par[slot][0][lane]      + s_par[slot][1][lane])      * rdn;
        float a1 = (s_par[slot][0][lane + 32] + s_par[slot][1][lane + 32]) * rdn;
        s_acc[lane][slot] = a0;
        if (lane + 32 < C_) s_acc[lane + 32][slot] = a1;
    }
    __syncthreads();

    // phase 3: 200 outputs per block
    int i = threadIdx.x;
    if (i < C_ * 4) {
        int c = i >> 2, j = i & 3;
        out[((size_t)b * C_ + c) * N_ + blockIdx.x * 4 + j] = s_acc[c][j];
    }
}

// Host-side stream/event objects, created ONCE at static-init time (host
// objects only; no device allocations in kernel_launch). Scatters on
// least-priority streams, lifts on greatest-priority streams so lift blocks
// jump the dispatch queue ahead of later batches' scatter blocks.
static cudaStream_t g_sstr[B_], g_lstr[B_];
static cudaEvent_t  g_root, g_evs[B_], g_evl[B_];
static const bool g_once = []() {
    int lo, hi;
    cudaDeviceGetStreamPriorityRange(&lo, &hi);   // hi = greatest priority
    for (int i = 0; i < B_; i++) {
        cudaStreamCreateWithPriority(&g_sstr[i], cudaStreamNonBlocking, lo);
        cudaStreamCreateWithPriority(&g_lstr[i], cudaStreamNonBlocking, hi);
    }
    cudaEventCreateWithFlags(&g_root, cudaEventDisableTiming);
    for (int i = 0; i < B_; i++) {
        cudaEventCreateWithFlags(&g_evs[i], cudaEventDisableTiming);
        cudaEventCreateWithFlags(&g_evl[i], cudaEventDisableTiming);
    }
    return true;
}();

extern "C" void kernel_launch(void* const* d_in, const int* in_sizes, int n_in,
                              void* d_out, int out_size) {
    // inputs: 0 points (unused), 1 predictions_2d, 2 rendered_pix_to_point,
    //         3 views_weights, 4 parts_nb
    const float* pred     = (const float*)d_in[1];
    const int*   p2p      = (const int*)  d_in[2];
    const float* vw       = (const float*)d_in[3];
    const int*   parts_nb = (const int*)  d_in[4];
    float*       out      = (float*)d_out;

    (void)g_once;

    cudaEventRecord(g_root, 0);
    for (int b = 0; b < B_; b++) {
        cudaStreamWaitEvent(g_sstr[b], g_root, 0);
        argmax_scatter_kernel<<<(V_ * P_) / 256, 256, 0, g_sstr[b]>>>(
            pred, p2p, parts_nb, b);
        cudaEventRecord(g_evs[b], g_sstr[b]);

        cudaStreamWaitEvent(g_lstr[b], g_evs[b], 0);
        lift_kernel<<<N_ / 4, 256, 0, g_lstr[b]>>>(vw, out, b);
        cudaEventRecord(g_evl[b], g_lstr[b]);
    }
    for (int b = 0; b < B_; b++)
        cudaStreamWaitEvent(0, g_evl[b], 0);
}